// round 3
// baseline (speedup 1.0000x reference)
#include <cuda_runtime.h>
#include <math.h>

// Problem constants
#define B   32
#define QL  16
#define KL  8192
#define D   512
#define INV_SQRT_D 0.044194173824159216f   // 1/sqrt(512)

#define KSPLIT 32
#define KCHUNK (KL / KSPLIT)     // 256

// Scratch (device globals; allocations forbidden)
__device__ float g_m[B * KSPLIT];            // local max per chunk
__device__ float g_z[B * KSPLIT];            // local exp-sum per chunk
__device__ float g_acc[B * KSPLIT * D];      // 2 MB: weighted-V partials

// ---------------------------------------------------------------------------
// Fused chunk kernel: for chunk (split, b) of 256 keys:
//   s_k  = (q0 . key_k)/sqrt(D) * t_k
//   m    = max_k s_k            (local)
//   p_k  = exp(s_k - m) * t_k
//   z    = sum p_k              (local)
//   acc  = sum_k p_k * value_k  (local, 512 floats)
// Streams K and V exactly once. grid (KSPLIT, B), block 256 (8 warps).
// ---------------------------------------------------------------------------
__global__ void attn_chunk_kernel(const float* __restrict__ q,
                                  const float* __restrict__ key,
                                  const float* __restrict__ value,
                                  const float* __restrict__ trust)
{
    const int b  = blockIdx.y;
    const int k0 = blockIdx.x * KCHUNK;
    const int tid  = threadIdx.x;
    const int warp = tid >> 5;
    const int lane = tid & 31;

    // All float4-accessed shared arrays must be 16B aligned (R2 fault: they
    // were plain float arrays, packed to a 4B-aligned offset).
    __shared__ __align__(16) float qs[D];       // 2 KB
    __shared__ __align__(16) float accbuf[D];   // 2 KB half-block merge
    __shared__ float ts[KCHUNK];                // 1 KB trust chunk
    __shared__ float ps[KCHUNK];                // 1 KB scores -> weights
    __shared__ float red[8];
    __shared__ float m_sh, z_sh;

    // stage q0 and trust chunk
    const float* qb = q + (size_t)b * QL * D;      // query[b, 0, :]
    for (int i = tid; i < D; i += 256) qs[i] = qb[i];
    const float* tb = trust + (size_t)b * KL + k0;
    for (int i = tid; i < KCHUNK; i += 256) ts[i] = tb[i];
    __syncthreads();

    // --- phase 1: scores (warp per key row), track local max ---
    const float4* qs4 = (const float4*)qs;
    float lmax = -INFINITY;
    for (int kk = warp; kk < KCHUNK; kk += 8) {
        const float4* kv4 = (const float4*)(key + ((size_t)b * KL + k0 + kk) * D);
        float acc = 0.0f;
        #pragma unroll
        for (int i = 0; i < 4; i++) {
            float4 kv = kv4[lane + i * 32];
            float4 qv = qs4[lane + i * 32];
            acc += kv.x * qv.x + kv.y * qv.y + kv.z * qv.z + kv.w * qv.w;
        }
        #pragma unroll
        for (int o = 16; o > 0; o >>= 1)
            acc += __shfl_xor_sync(0xffffffffu, acc, o);
        float s = acc * INV_SQRT_D * ts[kk];       // all lanes hold s
        if (lane == 0) ps[kk] = s;
        lmax = fmaxf(lmax, s);
    }
    // block max (lmax identical across lanes of a warp)
    if (lane == 0) red[warp] = lmax;
    __syncthreads();
    if (warp == 0) {
        float v = (lane < 8) ? red[lane] : -INFINITY;
        #pragma unroll
        for (int o = 4; o > 0; o >>= 1)
            v = fmaxf(v, __shfl_xor_sync(0xffffffffu, v, o));
        if (lane == 0) m_sh = v;
    }
    __syncthreads();
    const float m = m_sh;

    // --- phase 2: p_k = exp(s-m)*t, local z ---
    float lz = 0.0f;
    for (int i = tid; i < KCHUNK; i += 256) {
        float p = __expf(ps[i] - m) * ts[i];
        ps[i] = p;
        lz += p;
    }
    #pragma unroll
    for (int o = 16; o > 0; o >>= 1)
        lz += __shfl_xor_sync(0xffffffffu, lz, o);
    if (lane == 0) red[warp] = lz;
    __syncthreads();
    if (warp == 0) {
        float v = (lane < 8) ? red[lane] : 0.0f;
        #pragma unroll
        for (int o = 4; o > 0; o >>= 1)
            v += __shfl_xor_sync(0xffffffffu, v, o);
        if (lane == 0) z_sh = v;
    }
    __syncthreads();

    // --- phase 3: weighted V accumulation ---
    // half h handles rows kk = h, h+2, ...; each half covers all 128 float4 cols
    const int h = tid >> 7;            // 0 or 1
    const int t = tid & 127;           // float4 column
    const float4* vb = (const float4*)(value + ((size_t)b * KL + k0) * D) + t;

    float4 acc = make_float4(0.0f, 0.0f, 0.0f, 0.0f);
    #pragma unroll 8
    for (int kk = h; kk < KCHUNK; kk += 2) {
        float4 v = vb[(size_t)kk * (D / 4)];
        float  w = ps[kk];
        acc.x += w * v.x;
        acc.y += w * v.y;
        acc.z += w * v.z;
        acc.w += w * v.w;
    }

    // merge halves: half 0 stages, half 1 adds and writes partial
    if (h == 0) ((float4*)accbuf)[t] = acc;
    __syncthreads();
    if (h == 1) {
        float4 a0 = ((float4*)accbuf)[t];
        acc.x += a0.x; acc.y += a0.y; acc.z += a0.z; acc.w += a0.w;
        const size_t idx = (size_t)(b * KSPLIT + blockIdx.x);
        ((float4*)(g_acc + idx * D))[t] = acc;
        if (t == 0) { g_m[idx] = m; g_z[idx] = z_sh; }
    }
}

// ---------------------------------------------------------------------------
// Merge kernel: per batch, combine 32 chunk partials.
//   M = max m_i ; Z = sum z_i * exp(m_i - M)
//   out_d = sum_i exp(m_i - M) * acc_i[d] / Z
// grid (B), block 512 (one thread per d).
// ---------------------------------------------------------------------------
__global__ void merge_kernel(float* __restrict__ out)
{
    const int b = blockIdx.x;
    const int tid = threadIdx.x;

    __shared__ float scale_s[KSPLIT];

    if (tid < 32) {
        float mi = g_m[b * KSPLIT + tid];
        float zi = g_z[b * KSPLIT + tid];
        float M = mi;
        #pragma unroll
        for (int o = 16; o > 0; o >>= 1)
            M = fmaxf(M, __shfl_xor_sync(0xffffffffu, M, o));
        float e = __expf(mi - M);
        float Zp = zi * e;
        #pragma unroll
        for (int o = 16; o > 0; o >>= 1)
            Zp += __shfl_xor_sync(0xffffffffu, Zp, o);
        scale_s[tid] = e / Zp;
    }
    __syncthreads();

    float acc = 0.0f;
    #pragma unroll
    for (int i = 0; i < KSPLIT; i++)
        acc += scale_s[i] * g_acc[(size_t)(b * KSPLIT + i) * D + tid];
    out[(size_t)b * D + tid] = acc;
}

// ---------------------------------------------------------------------------
extern "C" void kernel_launch(void* const* d_in, const int* in_sizes, int n_in,
                              void* d_out, int out_size)
{
    const float* query = (const float*)d_in[0];   // (B, QL, D)
    const float* key   = (const float*)d_in[1];   // (B, KL, D)
    const float* value = (const float*)d_in[2];   // (B, KL, D)
    const float* trust = (const float*)d_in[3];   // (B, 1, KL)
    float* out = (float*)d_out;                   // (B, 1, D)

    (void)in_sizes; (void)n_in; (void)out_size;

    dim3 g1(KSPLIT, B);
    attn_chunk_kernel<<<g1, 256>>>(query, key, value, trust);

    merge_kernel<<<B, D>>>(out);
}